// round 11
// baseline (speedup 1.0000x reference)
#include <cuda_runtime.h>
#include <cstdint>
#include <cstddef>

// Problem constants (fixed by reference setup_inputs):
//   b=2, h=32, n=8192, d=128, e=128, BLOCK=64, num_block=128
//   query  [64, 8192, 128] f32, output [64, 8192, 128] f32 (added to),
//   s [32] f32, kv [64, 128, 128, 128] f32
//
// out[bh, blk*64+t, e] = output[...] + exp(-s[h]*(t+1)) * sum_d q[...]*kv[...]
//
// R11: 512 threads / 16 warps (4 per SMSP) to hide LDS/MMA/DRAM latency;
//      persistent CTAs, cp.async double buffer, oin register prefetch.

#define QS 132               // Q smem row stride (floats): A-frag conflict-free
#define KS 136               // KV smem row stride (floats): B-frag conflict-free
#define QTILEF (64 * QS)
#define KTILEF (128 * KS)
#define STAGEF (QTILEF + KTILEF)
#define SMEM_BYTES (2 * STAGEF * 4)   // 206,848 B

#define NTILES 8192          // 64 bh * 128 blocks
#define NT 512               // threads per CTA

__device__ __forceinline__ uint32_t f2tf32(float f) {
    uint32_t u;
    asm("cvt.rna.tf32.f32 %0, %1;" : "=r"(u) : "f"(f));
    return u;
}

__device__ __forceinline__ void cp16(uint32_t saddr, const float* g) {
    asm volatile("cp.async.cg.shared.global [%0], [%1], 16;\n"
                 :: "r"(saddr), "l"(g));
}

__global__ void __launch_bounds__(NT, 1)
lightning_inter_kernel(const float* __restrict__ q,
                       const float* __restrict__ oin,
                       const float* __restrict__ s,
                       const float* __restrict__ kv,
                       float* __restrict__ out,
                       int grid)
{
    extern __shared__ float smem[];
    const uint32_t sbase = (uint32_t)__cvta_generic_to_shared(smem);

    const int tid  = threadIdx.x;
    const int lane = tid & 31;
    const int warp = tid >> 5;       // 0..15
    const int wm   = warp & 1;       // M-range: rows [wm*32, +32)
    const int wn   = warp >> 1;      // 0..7 -> cols [wn*16, +16)
    const int gid  = lane >> 2;      // 0..7
    const int tig  = lane & 3;       // 0..3

    // ---- issue cp.async group for one tile into buffer `buf` ----
    auto stage = [&](int t, int buf) {
        const int bh = t >> 7, blk = t & 127;
        const float* qg = q  + ((size_t)bh * 8192 + (size_t)blk * 64) * 128;
        const float* kg = kv + ((size_t)bh * 128 + (size_t)blk) * 16384;
        const uint32_t sq = sbase + (uint32_t)buf * (STAGEF * 4);
        const uint32_t sk = sq + QTILEF * 4;
        #pragma unroll
        for (int i = 0; i < 4; i++) {             // Q: 2048 float4
            int idx = tid + i * NT;
            int row = idx >> 5, c4 = idx & 31;
            cp16(sq + (uint32_t)(row * QS + c4 * 4) * 4, qg + idx * 4);
        }
        #pragma unroll
        for (int i = 0; i < 8; i++) {             // KV: 4096 float4
            int idx = tid + i * NT;
            int row = idx >> 5, c4 = idx & 31;
            cp16(sk + (uint32_t)(row * KS + c4 * 4) * 4, kg + idx * 4);
        }
        asm volatile("cp.async.commit_group;\n");
    };

    int t = blockIdx.x;
    if (t < NTILES) stage(t, 0);

    int it = 0;
    for (; t < NTILES; t += grid, it++) {
        const int bh = t >> 7, blk = t & 127;
        const size_t obase = (size_t)bh * 8192 + (size_t)blk * 64;
        const float sv = s[bh & 31];

        // ---- prefetch oin for this tile into registers ----
        float2 orf[2][2][2];
        #pragma unroll
        for (int mi = 0; mi < 2; mi++) {
            const int r0 = wm * 32 + mi * 16 + gid;
            #pragma unroll
            for (int ni = 0; ni < 2; ni++) {
                const int col = wn * 16 + ni * 8 + tig * 2;
                orf[mi][ni][0] = *(const float2*)&oin[(obase + r0) * 128 + col];
                orf[mi][ni][1] = *(const float2*)&oin[(obase + r0 + 8) * 128 + col];
            }
        }

        // ---- prefetch next tile, wait for this one ----
        const int tn = t + grid;
        if (tn < NTILES) {
            stage(tn, (it + 1) & 1);
            asm volatile("cp.async.wait_group 1;\n");
        } else {
            asm volatile("cp.async.wait_group 0;\n");
        }
        __syncthreads();

        const float* sQ  = smem + (it & 1) * STAGEF;
        const float* sKV = sQ + QTILEF;

        float acc[2][2][4];
        #pragma unroll
        for (int mi = 0; mi < 2; mi++)
            #pragma unroll
            for (int ni = 0; ni < 2; ni++)
                #pragma unroll
                for (int r = 0; r < 4; r++) acc[mi][ni][r] = 0.0f;

        // ---- mainloop: 16 k-steps of m16n8k8 tf32, warp tile 32x16 ----
        #pragma unroll
        for (int ks = 0; ks < 16; ks++) {
            const int k0 = ks * 8;

            uint32_t af[2][4];
            #pragma unroll
            for (int mi = 0; mi < 2; mi++) {
                const int rb = wm * 32 + mi * 16 + gid;
                const float* base = &sQ[rb * QS + k0 + tig];
                af[mi][0] = f2tf32(base[0]);
                af[mi][1] = f2tf32(base[8 * QS]);
                af[mi][2] = f2tf32(base[4]);
                af[mi][3] = f2tf32(base[8 * QS + 4]);
            }

            uint32_t bf[2][2];
            #pragma unroll
            for (int ni = 0; ni < 2; ni++) {
                const int cb = wn * 16 + ni * 8 + gid;
                const float* base = &sKV[(k0 + tig) * KS + cb];
                bf[ni][0] = f2tf32(base[0]);
                bf[ni][1] = f2tf32(base[4 * KS]);
            }

            #pragma unroll
            for (int mi = 0; mi < 2; mi++)
                #pragma unroll
                for (int ni = 0; ni < 2; ni++) {
                    asm volatile(
                        "mma.sync.aligned.m16n8k8.row.col.f32.tf32.tf32.f32 "
                        "{%0,%1,%2,%3}, {%4,%5,%6,%7}, {%8,%9}, {%0,%1,%2,%3};\n"
                        : "+f"(acc[mi][ni][0]), "+f"(acc[mi][ni][1]),
                          "+f"(acc[mi][ni][2]), "+f"(acc[mi][ni][3])
                        : "r"(af[mi][0]), "r"(af[mi][1]), "r"(af[mi][2]), "r"(af[mi][3]),
                          "r"(bf[ni][0]), "r"(bf[ni][1]));
                }
        }
        __syncthreads();   // smem reads done -> buffer may be overwritten next iter

        // ---- epilogue: out = oin + exp(-s*(t+1)) * acc ----
        #pragma unroll
        for (int mi = 0; mi < 2; mi++) {
            const int r0 = wm * 32 + mi * 16 + gid;
            const float d0 = __expf(-sv * (float)(r0 + 1));
            const float d1 = __expf(-sv * (float)(r0 + 9));
            #pragma unroll
            for (int ni = 0; ni < 2; ni++) {
                const int col = wn * 16 + ni * 8 + tig * 2;
                float2 o0 = orf[mi][ni][0];
                o0.x += d0 * acc[mi][ni][0];
                o0.y += d0 * acc[mi][ni][1];
                *(float2*)&out[(obase + r0) * 128 + col] = o0;
                float2 o1 = orf[mi][ni][1];
                o1.x += d1 * acc[mi][ni][2];
                o1.y += d1 * acc[mi][ni][3];
                *(float2*)&out[(obase + r0 + 8) * 128 + col] = o1;
            }
        }
    }
}

extern "C" void kernel_launch(void* const* d_in, const int* in_sizes, int n_in,
                              void* d_out, int out_size)
{
    const float* q   = (const float*)d_in[0];
    const float* oin = (const float*)d_in[1];
    const float* s   = (const float*)d_in[2];
    const float* kv  = (const float*)d_in[3];
    float* out = (float*)d_out;

    int dev = 0;
    cudaGetDevice(&dev);
    int nsm = 148;
    cudaDeviceGetAttribute(&nsm, cudaDevAttrMultiProcessorCount, dev);

    cudaFuncSetAttribute(lightning_inter_kernel,
                         cudaFuncAttributeMaxDynamicSharedMemorySize, SMEM_BYTES);

    lightning_inter_kernel<<<nsm, NT, SMEM_BYTES>>>(q, oin, s, kv, out, nsm);
}

// round 12
// speedup vs baseline: 1.0764x; 1.0764x over previous
#include <cuda_runtime.h>
#include <cstdint>
#include <cstddef>

// Problem constants (fixed by reference setup_inputs):
//   b=2, h=32, n=8192, d=128, e=128, BLOCK=64, num_block=128
//   query  [64, 8192, 128] f32, output [64, 8192, 128] f32 (added to),
//   s [32] f32, kv [64, 128, 128, 128] f32
//
// out[bh, blk*64+t, e] = output[...] + exp(-s[h]*(t+1)) * sum_d q[...]*kv[...]
//
// R12: ldmatrix.x4 for A fragments (raw fp32 -> tf32 truncation), B keeps
//      cvt.rna; 16 warps (4/SMSP); persistent CTAs + cp.async double buffer.

#define QS 132               // Q smem row stride (floats): LDSM/A conflict-free
#define KS 136               // KV smem row stride (floats): B-frag conflict-free
#define QTILEF (64 * QS)
#define KTILEF (128 * KS)
#define STAGEF (QTILEF + KTILEF)
#define SMEM_BYTES (2 * STAGEF * 4)   // 206,848 B

#define NTILES 8192          // 64 bh * 128 blocks
#define NT 512               // threads per CTA

__device__ __forceinline__ uint32_t f2tf32(float f) {
    uint32_t u;
    asm("cvt.rna.tf32.f32 %0, %1;" : "=r"(u) : "f"(f));
    return u;
}

__device__ __forceinline__ void cp16(uint32_t saddr, const float* g) {
    asm volatile("cp.async.cg.shared.global [%0], [%1], 16;\n"
                 :: "r"(saddr), "l"(g));
}

__global__ void __launch_bounds__(NT, 1)
lightning_inter_kernel(const float* __restrict__ q,
                       const float* __restrict__ oin,
                       const float* __restrict__ s,
                       const float* __restrict__ kv,
                       float* __restrict__ out,
                       int grid)
{
    extern __shared__ float smem[];
    const uint32_t sbase = (uint32_t)__cvta_generic_to_shared(smem);

    const int tid  = threadIdx.x;
    const int lane = tid & 31;
    const int warp = tid >> 5;       // 0..15
    const int wm   = warp & 1;       // M-range: rows [wm*32, +32)
    const int wn   = warp >> 1;      // 0..7 -> cols [wn*16, +16)
    const int gid  = lane >> 2;      // 0..7
    const int tig  = lane & 3;       // 0..3

    // Per-lane ldmatrix offsets (bytes, relative to sQ buffer base), one per mi.
    // x4 tile order: t0=rows(+0..7)cols(k0..k0+3), t1=rows(+8..15), t2=cols(+4..7), t3=both.
    uint32_t a_off[2];
    #pragma unroll
    for (int mi = 0; mi < 2; mi++) {
        int row = wm * 32 + mi * 16 + (lane & 7) + (lane & 8);
        a_off[mi] = (uint32_t)(row * QS + ((lane >> 4) << 2)) * 4;
    }

    // ---- issue cp.async group for one tile into buffer `buf` ----
    auto stage = [&](int t, int buf) {
        const int bh = t >> 7, blk = t & 127;
        const float* qg = q  + ((size_t)bh * 8192 + (size_t)blk * 64) * 128;
        const float* kg = kv + ((size_t)bh * 128 + (size_t)blk) * 16384;
        const uint32_t sq = sbase + (uint32_t)buf * (STAGEF * 4);
        const uint32_t sk = sq + QTILEF * 4;
        #pragma unroll
        for (int i = 0; i < 4; i++) {             // Q: 2048 float4
            int idx = tid + i * NT;
            int row = idx >> 5, c4 = idx & 31;
            cp16(sq + (uint32_t)(row * QS + c4 * 4) * 4, qg + idx * 4);
        }
        #pragma unroll
        for (int i = 0; i < 8; i++) {             // KV: 4096 float4
            int idx = tid + i * NT;
            int row = idx >> 5, c4 = idx & 31;
            cp16(sk + (uint32_t)(row * KS + c4 * 4) * 4, kg + idx * 4);
        }
        asm volatile("cp.async.commit_group;\n");
    };

    int t = blockIdx.x;
    if (t < NTILES) stage(t, 0);

    int it = 0;
    for (; t < NTILES; t += grid, it++) {
        const int bh = t >> 7, blk = t & 127;
        const size_t obase = (size_t)bh * 8192 + (size_t)blk * 64;
        const float sv = s[bh & 31];

        // ---- prefetch oin for this tile into registers ----
        float2 orf[2][2][2];
        #pragma unroll
        for (int mi = 0; mi < 2; mi++) {
            const int r0 = wm * 32 + mi * 16 + gid;
            #pragma unroll
            for (int ni = 0; ni < 2; ni++) {
                const int col = wn * 16 + ni * 8 + tig * 2;
                orf[mi][ni][0] = *(const float2*)&oin[(obase + r0) * 128 + col];
                orf[mi][ni][1] = *(const float2*)&oin[(obase + r0 + 8) * 128 + col];
            }
        }

        // ---- prefetch next tile, wait for this one ----
        const int tn = t + grid;
        if (tn < NTILES) {
            stage(tn, (it + 1) & 1);
            asm volatile("cp.async.wait_group 1;\n");
        } else {
            asm volatile("cp.async.wait_group 0;\n");
        }
        __syncthreads();

        const uint32_t sq_u = sbase + (uint32_t)(it & 1) * (STAGEF * 4);
        const float*   sKV  = smem + (it & 1) * STAGEF + QTILEF;

        float acc[2][2][4];
        #pragma unroll
        for (int mi = 0; mi < 2; mi++)
            #pragma unroll
            for (int ni = 0; ni < 2; ni++)
                #pragma unroll
                for (int r = 0; r < 4; r++) acc[mi][ni][r] = 0.0f;

        // ---- mainloop: 16 k-steps of m16n8k8 tf32, warp tile 32x16 ----
        #pragma unroll
        for (int ks = 0; ks < 16; ks++) {
            const int k0 = ks * 8;

            uint32_t af[2][4];
            #pragma unroll
            for (int mi = 0; mi < 2; mi++) {
                asm volatile(
                    "ldmatrix.sync.aligned.m8n8.x4.shared.b16 {%0,%1,%2,%3}, [%4];\n"
                    : "=r"(af[mi][0]), "=r"(af[mi][1]),
                      "=r"(af[mi][2]), "=r"(af[mi][3])
                    : "r"(sq_u + a_off[mi] + (uint32_t)(k0 * 4)));
            }

            uint32_t bf[2][2];
            #pragma unroll
            for (int ni = 0; ni < 2; ni++) {
                const int cb = wn * 16 + ni * 8 + gid;
                const float* base = &sKV[(k0 + tig) * KS + cb];
                bf[ni][0] = f2tf32(base[0]);
                bf[ni][1] = f2tf32(base[4 * KS]);
            }

            #pragma unroll
            for (int mi = 0; mi < 2; mi++)
                #pragma unroll
                for (int ni = 0; ni < 2; ni++) {
                    asm volatile(
                        "mma.sync.aligned.m16n8k8.row.col.f32.tf32.tf32.f32 "
                        "{%0,%1,%2,%3}, {%4,%5,%6,%7}, {%8,%9}, {%0,%1,%2,%3};\n"
                        : "+f"(acc[mi][ni][0]), "+f"(acc[mi][ni][1]),
                          "+f"(acc[mi][ni][2]), "+f"(acc[mi][ni][3])
                        : "r"(af[mi][0]), "r"(af[mi][1]), "r"(af[mi][2]), "r"(af[mi][3]),
                          "r"(bf[ni][0]), "r"(bf[ni][1]));
                }
        }
        __syncthreads();   // smem reads done -> buffer may be overwritten next iter

        // ---- epilogue: out = oin + exp(-s*(t+1)) * acc ----
        #pragma unroll
        for (int mi = 0; mi < 2; mi++) {
            const int r0 = wm * 32 + mi * 16 + gid;
            const float d0 = __expf(-sv * (float)(r0 + 1));
            const float d1 = __expf(-sv * (float)(r0 + 9));
            #pragma unroll
            for (int ni = 0; ni < 2; ni++) {
                const int col = wn * 16 + ni * 8 + tig * 2;
                float2 o0 = orf[mi][ni][0];
                o0.x += d0 * acc[mi][ni][0];
                o0.y += d0 * acc[mi][ni][1];
                *(float2*)&out[(obase + r0) * 128 + col] = o0;
                float2 o1 = orf[mi][ni][1];
                o1.x += d1 * acc[mi][ni][2];
                o1.y += d1 * acc[mi][ni][3];
                *(float2*)&out[(obase + r0 + 8) * 128 + col] = o1;
            }
        }
    }
}

extern "C" void kernel_launch(void* const* d_in, const int* in_sizes, int n_in,
                              void* d_out, int out_size)
{
    const float* q   = (const float*)d_in[0];
    const float* oin = (const float*)d_in[1];
    const float* s   = (const float*)d_in[2];
    const float* kv  = (const float*)d_in[3];
    float* out = (float*)d_out;

    int dev = 0;
    cudaGetDevice(&dev);
    int nsm = 148;
    cudaDeviceGetAttribute(&nsm, cudaDevAttrMultiProcessorCount, dev);

    cudaFuncSetAttribute(lightning_inter_kernel,
                         cudaFuncAttributeMaxDynamicSharedMemorySize, SMEM_BYTES);

    lightning_inter_kernel<<<nsm, NT, SMEM_BYTES>>>(q, oin, s, kv, out, nsm);
}

// round 13
// speedup vs baseline: 1.0870x; 1.0098x over previous
#include <cuda_runtime.h>
#include <cstdint>
#include <cstddef>

// Problem constants (fixed by reference setup_inputs):
//   b=2, h=32, n=8192, d=128, e=128, BLOCK=64, num_block=128
//   query  [64, 8192, 128] f32, output [64, 8192, 128] f32 (added to),
//   s [32] f32, kv [64, 128, 128, 128] f32
//
// out[bh, blk*64+t, e] = output[...] + exp(-s[h]*(t+1)) * sum_d q[...]*kv[...]
//
// R13: chunked staging — each tile staged as two 48KB commit groups issued at
//      two points in the mainloop (anti-convoy smoothing of DRAM demand).
//      16 warps, ldmatrix A-path, persistent CTAs, double buffer.

#define QS 132               // Q smem row stride (floats): LDSM/A conflict-free
#define KS 136               // KV smem row stride (floats): B-frag conflict-free
#define QTILEF (64 * QS)
#define KTILEF (128 * KS)
#define STAGEF (QTILEF + KTILEF)
#define SMEM_BYTES (2 * STAGEF * 4)   // 206,848 B

#define NTILES 8192          // 64 bh * 128 blocks
#define NT 512               // threads per CTA

__device__ __forceinline__ uint32_t f2tf32(float f) {
    uint32_t u;
    asm("cvt.rna.tf32.f32 %0, %1;" : "=r"(u) : "f"(f));
    return u;
}

__device__ __forceinline__ void cp16(uint32_t saddr, const float* g) {
    asm volatile("cp.async.cg.shared.global [%0], [%1], 16;\n"
                 :: "r"(saddr), "l"(g));
}

__global__ void __launch_bounds__(NT, 1)
lightning_inter_kernel(const float* __restrict__ q,
                       const float* __restrict__ oin,
                       const float* __restrict__ s,
                       const float* __restrict__ kv,
                       float* __restrict__ out,
                       int grid)
{
    extern __shared__ float smem[];
    const uint32_t sbase = (uint32_t)__cvta_generic_to_shared(smem);

    const int tid  = threadIdx.x;
    const int lane = tid & 31;
    const int warp = tid >> 5;       // 0..15
    const int wm   = warp & 1;       // M-range: rows [wm*32, +32)
    const int wn   = warp >> 1;      // 0..7 -> cols [wn*16, +16)
    const int gid  = lane >> 2;      // 0..7
    const int tig  = lane & 3;       // 0..3

    // Per-lane ldmatrix byte offsets (relative to sQ base), one per mi.
    uint32_t a_off[2];
    #pragma unroll
    for (int mi = 0; mi < 2; mi++) {
        int row = wm * 32 + mi * 16 + (lane & 7) + (lane & 8);
        a_off[mi] = (uint32_t)(row * QS + ((lane >> 4) << 2)) * 4;
    }

    // ---- chunk A: Q cols [0,64) + KV rows [0,64)  (48 KB) ----
    auto stageA = [&](int t, int buf) {
        const int bh = t >> 7, blk = t & 127;
        const float* qg = q  + ((size_t)bh * 8192 + (size_t)blk * 64) * 128;
        const float* kg = kv + ((size_t)bh * 128 + (size_t)blk) * 16384;
        const uint32_t sq = sbase + (uint32_t)buf * (STAGEF * 4);
        const uint32_t sk = sq + QTILEF * 4;
        #pragma unroll
        for (int i = 0; i < 2; i++) {             // Q left half: 1024 float4
            int idx = tid + i * NT;               // 0..1023
            int row = idx >> 4, c4 = idx & 15;    // cols 0..63
            cp16(sq + (uint32_t)(row * QS + c4 * 4) * 4, qg + row * 128 + c4 * 4);
        }
        #pragma unroll
        for (int i = 0; i < 4; i++) {             // KV rows 0..63: 2048 float4
            int idx = tid + i * NT;               // 0..2047
            int row = idx >> 5, c4 = idx & 31;
            cp16(sk + (uint32_t)(row * KS + c4 * 4) * 4, kg + idx * 4);
        }
        asm volatile("cp.async.commit_group;\n");
    };
    // ---- chunk B: Q cols [64,128) + KV rows [64,128)  (48 KB) ----
    auto stageB = [&](int t, int buf) {
        const int bh = t >> 7, blk = t & 127;
        const float* qg = q  + ((size_t)bh * 8192 + (size_t)blk * 64) * 128;
        const float* kg = kv + ((size_t)bh * 128 + (size_t)blk) * 16384;
        const uint32_t sq = sbase + (uint32_t)buf * (STAGEF * 4);
        const uint32_t sk = sq + QTILEF * 4;
        #pragma unroll
        for (int i = 0; i < 2; i++) {
            int idx = tid + i * NT;
            int row = idx >> 4, c4 = (idx & 15) + 16;   // cols 64..127
            cp16(sq + (uint32_t)(row * QS + c4 * 4) * 4, qg + row * 128 + c4 * 4);
        }
        #pragma unroll
        for (int i = 0; i < 4; i++) {
            int idx = tid + i * NT + 2048;        // 2048..4095 -> rows 64..127
            int row = idx >> 5, c4 = idx & 31;
            cp16(sk + (uint32_t)(row * KS + c4 * 4) * 4, kg + idx * 4);
        }
        asm volatile("cp.async.commit_group;\n");
    };

    int t = blockIdx.x;
    if (t < NTILES) { stageA(t, 0); stageB(t, 0); }   // pending: A(t), B(t)

    int it = 0;
    for (; t < NTILES; t += grid, it++) {
        const int bh = t >> 7, blk = t & 127;
        const size_t obase = (size_t)bh * 8192 + (size_t)blk * 64;
        const float sv = s[bh & 31];
        const int buf = it & 1;
        const int tn = t + grid;

        // ---- prefetch oin for this tile into registers ----
        float2 orf[2][2][2];
        #pragma unroll
        for (int mi = 0; mi < 2; mi++) {
            const int r0 = wm * 32 + mi * 16 + gid;
            #pragma unroll
            for (int ni = 0; ni < 2; ni++) {
                const int col = wn * 16 + ni * 8 + tig * 2;
                orf[mi][ni][0] = *(const float2*)&oin[(obase + r0) * 128 + col];
                orf[mi][ni][1] = *(const float2*)&oin[(obase + r0 + 8) * 128 + col];
            }
        }

        // ---- issue chunk A of next tile; wait for chunk A of this tile ----
        if (tn < NTILES) {
            stageA(tn, buf ^ 1);                          // pending: A(t),B(t),A(tn)
            asm volatile("cp.async.wait_group 2;\n");     // A(t) done
        } else {
            asm volatile("cp.async.wait_group 1;\n");     // pending: A(t),B(t) -> A(t) done
        }
        __syncthreads();

        const uint32_t sq_u = sbase + (uint32_t)buf * (STAGEF * 4);
        const float*   sKV  = smem + buf * STAGEF + QTILEF;

        float acc[2][2][4];
        #pragma unroll
        for (int mi = 0; mi < 2; mi++)
            #pragma unroll
            for (int ni = 0; ni < 2; ni++)
                #pragma unroll
                for (int r = 0; r < 4; r++) acc[mi][ni][r] = 0.0f;

        // ---- k-steps 0..7 (chunk A data) ----
        #pragma unroll
        for (int ks = 0; ks < 8; ks++) {
            const int k0 = ks * 8;
            uint32_t af[2][4];
            #pragma unroll
            for (int mi = 0; mi < 2; mi++) {
                asm volatile(
                    "ldmatrix.sync.aligned.m8n8.x4.shared.b16 {%0,%1,%2,%3}, [%4];\n"
                    : "=r"(af[mi][0]), "=r"(af[mi][1]),
                      "=r"(af[mi][2]), "=r"(af[mi][3])
                    : "r"(sq_u + a_off[mi] + (uint32_t)(k0 * 4)));
            }
            uint32_t bf[2][2];
            #pragma unroll
            for (int ni = 0; ni < 2; ni++) {
                const int cb = wn * 16 + ni * 8 + gid;
                const float* base = &sKV[(k0 + tig) * KS + cb];
                bf[ni][0] = f2tf32(base[0]);
                bf[ni][1] = f2tf32(base[4 * KS]);
            }
            #pragma unroll
            for (int mi = 0; mi < 2; mi++)
                #pragma unroll
                for (int ni = 0; ni < 2; ni++) {
                    asm volatile(
                        "mma.sync.aligned.m16n8k8.row.col.f32.tf32.tf32.f32 "
                        "{%0,%1,%2,%3}, {%4,%5,%6,%7}, {%8,%9}, {%0,%1,%2,%3};\n"
                        : "+f"(acc[mi][ni][0]), "+f"(acc[mi][ni][1]),
                          "+f"(acc[mi][ni][2]), "+f"(acc[mi][ni][3])
                        : "r"(af[mi][0]), "r"(af[mi][1]), "r"(af[mi][2]), "r"(af[mi][3]),
                          "r"(bf[ni][0]), "r"(bf[ni][1]));
                }
        }

        // ---- issue chunk B of next tile; wait for chunk B of this tile ----
        if (tn < NTILES) {
            stageB(tn, buf ^ 1);                          // pending: B(t),A(tn),B(tn)
            asm volatile("cp.async.wait_group 2;\n");     // B(t) done
        } else {
            asm volatile("cp.async.wait_group 0;\n");
        }
        __syncthreads();

        // ---- k-steps 8..15 (chunk B data) ----
        #pragma unroll
        for (int ks = 8; ks < 16; ks++) {
            const int k0 = ks * 8;
            uint32_t af[2][4];
            #pragma unroll
            for (int mi = 0; mi < 2; mi++) {
                asm volatile(
                    "ldmatrix.sync.aligned.m8n8.x4.shared.b16 {%0,%1,%2,%3}, [%4];\n"
                    : "=r"(af[mi][0]), "=r"(af[mi][1]),
                      "=r"(af[mi][2]), "=r"(af[mi][3])
                    : "r"(sq_u + a_off[mi] + (uint32_t)(k0 * 4)));
            }
            uint32_t bf[2][2];
            #pragma unroll
            for (int ni = 0; ni < 2; ni++) {
                const int cb = wn * 16 + ni * 8 + gid;
                const float* base = &sKV[(k0 + tig) * KS + cb];
                bf[ni][0] = f2tf32(base[0]);
                bf[ni][1] = f2tf32(base[4 * KS]);
            }
            #pragma unroll
            for (int mi = 0; mi < 2; mi++)
                #pragma unroll
                for (int ni = 0; ni < 2; ni++) {
                    asm volatile(
                        "mma.sync.aligned.m16n8k8.row.col.f32.tf32.tf32.f32 "
                        "{%0,%1,%2,%3}, {%4,%5,%6,%7}, {%8,%9}, {%0,%1,%2,%3};\n"
                        : "+f"(acc[mi][ni][0]), "+f"(acc[mi][ni][1]),
                          "+f"(acc[mi][ni][2]), "+f"(acc[mi][ni][3])
                        : "r"(af[mi][0]), "r"(af[mi][1]), "r"(af[mi][2]), "r"(af[mi][3]),
                          "r"(bf[ni][0]), "r"(bf[ni][1]));
                }
        }
        __syncthreads();   // all reads of buf done before next iter stages into it

        // ---- epilogue: out = oin + exp(-s*(t+1)) * acc ----
        #pragma unroll
        for (int mi = 0; mi < 2; mi++) {
            const int r0 = wm * 32 + mi * 16 + gid;
            const float d0 = __expf(-sv * (float)(r0 + 1));
            const float d1 = __expf(-sv * (float)(r0 + 9));
            #pragma unroll
            for (int ni = 0; ni < 2; ni++) {
                const int col = wn * 16 + ni * 8 + tig * 2;
                float2 o0 = orf[mi][ni][0];
                o0.x += d0 * acc[mi][ni][0];
                o0.y += d0 * acc[mi][ni][1];
                *(float2*)&out[(obase + r0) * 128 + col] = o0;
                float2 o1 = orf[mi][ni][1];
                o1.x += d1 * acc[mi][ni][2];
                o1.y += d1 * acc[mi][ni][3];
                *(float2*)&out[(obase + r0 + 8) * 128 + col] = o1;
            }
        }
    }
}

extern "C" void kernel_launch(void* const* d_in, const int* in_sizes, int n_in,
                              void* d_out, int out_size)
{
    const float* q   = (const float*)d_in[0];
    const float* oin = (const float*)d_in[1];
    const float* s   = (const float*)d_in[2];
    const float* kv  = (const float*)d_in[3];
    float* out = (float*)d_out;

    int dev = 0;
    cudaGetDevice(&dev);
    int nsm = 148;
    cudaDeviceGetAttribute(&nsm, cudaDevAttrMultiProcessorCount, dev);

    cudaFuncSetAttribute(lightning_inter_kernel,
                         cudaFuncAttributeMaxDynamicSharedMemorySize, SMEM_BYTES);

    lightning_inter_kernel<<<nsm, NT, SMEM_BYTES>>>(q, oin, s, kv, out, nsm);
}

// round 14
// speedup vs baseline: 1.0991x; 1.0111x over previous
#include <cuda_runtime.h>
#include <cstdint>
#include <cstddef>

// Problem constants (fixed by reference setup_inputs):
//   b=2, h=32, n=8192, d=128, e=128, BLOCK=64, num_block=128
//   query  [64, 8192, 128] f32, output [64, 8192, 128] f32 (added to),
//   s [32] f32, kv [64, 128, 128, 128] f32
//
// out[bh, blk*64+t, e] = output[...] + exp(-s[h]*(t+1)) * sum_d q[...]*kv[...]
//
// R14: full-line-coalesced epilogue via smem bounce (fragments -> smem ->
//      linear float4 LDG/STG covering whole 128B lines). Everything else
//      kept from R13: 16 warps, ldmatrix A-path, chunked cp.async double
//      buffer, persistent CTAs.

#define QS 132               // Q smem row stride (floats): LDSM/A conflict-free
#define KS 136               // KV smem row stride (floats): B-frag conflict-free
#define OSD 132              // O bounce stride (reuses Q area; needs <= QS)
#define QTILEF (64 * QS)
#define KTILEF (128 * KS)
#define STAGEF (QTILEF + KTILEF)
#define SMEM_BYTES (2 * STAGEF * 4)   // 206,848 B

#define NTILES 8192          // 64 bh * 128 blocks
#define NT 512               // threads per CTA

__device__ __forceinline__ uint32_t f2tf32(float f) {
    uint32_t u;
    asm("cvt.rna.tf32.f32 %0, %1;" : "=r"(u) : "f"(f));
    return u;
}

__device__ __forceinline__ void cp16(uint32_t saddr, const float* g) {
    asm volatile("cp.async.cg.shared.global [%0], [%1], 16;\n"
                 :: "r"(saddr), "l"(g));
}

__global__ void __launch_bounds__(NT, 1)
lightning_inter_kernel(const float* __restrict__ q,
                       const float* __restrict__ oin,
                       const float* __restrict__ s,
                       const float* __restrict__ kv,
                       float* __restrict__ out,
                       int grid)
{
    extern __shared__ float smem[];
    const uint32_t sbase = (uint32_t)__cvta_generic_to_shared(smem);

    const int tid  = threadIdx.x;
    const int lane = tid & 31;
    const int warp = tid >> 5;       // 0..15
    const int wm   = warp & 1;       // M-range: rows [wm*32, +32)
    const int wn   = warp >> 1;      // 0..7 -> cols [wn*16, +16)
    const int gid  = lane >> 2;      // 0..7
    const int tig  = lane & 3;       // 0..3

    // Per-lane ldmatrix byte offsets (relative to sQ base), one per mi.
    uint32_t a_off[2];
    #pragma unroll
    for (int mi = 0; mi < 2; mi++) {
        int row = wm * 32 + mi * 16 + (lane & 7) + (lane & 8);
        a_off[mi] = (uint32_t)(row * QS + ((lane >> 4) << 2)) * 4;
    }

    // ---- chunk A: Q cols [0,64) + KV rows [0,64)  (48 KB) ----
    auto stageA = [&](int t, int buf) {
        const int bh = t >> 7, blk = t & 127;
        const float* qg = q  + ((size_t)bh * 8192 + (size_t)blk * 64) * 128;
        const float* kg = kv + ((size_t)bh * 128 + (size_t)blk) * 16384;
        const uint32_t sq = sbase + (uint32_t)buf * (STAGEF * 4);
        const uint32_t sk = sq + QTILEF * 4;
        #pragma unroll
        for (int i = 0; i < 2; i++) {             // Q left half: 1024 float4
            int idx = tid + i * NT;               // 0..1023
            int row = idx >> 4, c4 = idx & 15;    // cols 0..63
            cp16(sq + (uint32_t)(row * QS + c4 * 4) * 4, qg + row * 128 + c4 * 4);
        }
        #pragma unroll
        for (int i = 0; i < 4; i++) {             // KV rows 0..63: 2048 float4
            int idx = tid + i * NT;               // 0..2047
            int row = idx >> 5, c4 = idx & 31;
            cp16(sk + (uint32_t)(row * KS + c4 * 4) * 4, kg + idx * 4);
        }
        asm volatile("cp.async.commit_group;\n");
    };
    // ---- chunk B: Q cols [64,128) + KV rows [64,128)  (48 KB) ----
    auto stageB = [&](int t, int buf) {
        const int bh = t >> 7, blk = t & 127;
        const float* qg = q  + ((size_t)bh * 8192 + (size_t)blk * 64) * 128;
        const float* kg = kv + ((size_t)bh * 128 + (size_t)blk) * 16384;
        const uint32_t sq = sbase + (uint32_t)buf * (STAGEF * 4);
        const uint32_t sk = sq + QTILEF * 4;
        #pragma unroll
        for (int i = 0; i < 2; i++) {
            int idx = tid + i * NT;
            int row = idx >> 4, c4 = (idx & 15) + 16;   // cols 64..127
            cp16(sq + (uint32_t)(row * QS + c4 * 4) * 4, qg + row * 128 + c4 * 4);
        }
        #pragma unroll
        for (int i = 0; i < 4; i++) {
            int idx = tid + i * NT + 2048;        // 2048..4095 -> rows 64..127
            int row = idx >> 5, c4 = idx & 31;
            cp16(sk + (uint32_t)(row * KS + c4 * 4) * 4, kg + idx * 4);
        }
        asm volatile("cp.async.commit_group;\n");
    };

    int t = blockIdx.x;
    if (t < NTILES) { stageA(t, 0); stageB(t, 0); }   // pending: A(t), B(t)

    int it = 0;
    for (; t < NTILES; t += grid, it++) {
        const int bh = t >> 7, blk = t & 127;
        const size_t obase = (size_t)bh * 8192 + (size_t)blk * 64;
        const float sv = s[bh & 31];
        const int buf = it & 1;
        const int tn = t + grid;

        // ---- prefetch oin linearly (full-line coalesced) into registers ----
        float4 oreg[4];
        #pragma unroll
        for (int j = 0; j < 4; j++) {
            int f = tid + j * NT;                 // float4 index 0..2047
            int row = f >> 5, c4 = f & 31;
            oreg[j] = *(const float4*)&oin[(obase + row) * 128 + c4 * 4];
        }

        // ---- issue chunk A of next tile; wait for chunk A of this tile ----
        if (tn < NTILES) {
            stageA(tn, buf ^ 1);                          // pending: A(t),B(t),A(tn)
            asm volatile("cp.async.wait_group 2;\n");     // A(t) done
        } else {
            asm volatile("cp.async.wait_group 1;\n");
        }
        __syncthreads();

        const uint32_t sq_u = sbase + (uint32_t)buf * (STAGEF * 4);
        const float*   sKV  = smem + buf * STAGEF + QTILEF;
        float*         sO   = smem + buf * STAGEF;       // reuse Q area (dead after mainloop)

        float acc[2][2][4];
        #pragma unroll
        for (int mi = 0; mi < 2; mi++)
            #pragma unroll
            for (int ni = 0; ni < 2; ni++)
                #pragma unroll
                for (int r = 0; r < 4; r++) acc[mi][ni][r] = 0.0f;

        // ---- k-steps 0..7 (chunk A data) ----
        #pragma unroll
        for (int ks = 0; ks < 8; ks++) {
            const int k0 = ks * 8;
            uint32_t af[2][4];
            #pragma unroll
            for (int mi = 0; mi < 2; mi++) {
                asm volatile(
                    "ldmatrix.sync.aligned.m8n8.x4.shared.b16 {%0,%1,%2,%3}, [%4];\n"
                    : "=r"(af[mi][0]), "=r"(af[mi][1]),
                      "=r"(af[mi][2]), "=r"(af[mi][3])
                    : "r"(sq_u + a_off[mi] + (uint32_t)(k0 * 4)));
            }
            uint32_t bf[2][2];
            #pragma unroll
            for (int ni = 0; ni < 2; ni++) {
                const int cb = wn * 16 + ni * 8 + gid;
                const float* base = &sKV[(k0 + tig) * KS + cb];
                bf[ni][0] = f2tf32(base[0]);
                bf[ni][1] = f2tf32(base[4 * KS]);
            }
            #pragma unroll
            for (int mi = 0; mi < 2; mi++)
                #pragma unroll
                for (int ni = 0; ni < 2; ni++) {
                    asm volatile(
                        "mma.sync.aligned.m16n8k8.row.col.f32.tf32.tf32.f32 "
                        "{%0,%1,%2,%3}, {%4,%5,%6,%7}, {%8,%9}, {%0,%1,%2,%3};\n"
                        : "+f"(acc[mi][ni][0]), "+f"(acc[mi][ni][1]),
                          "+f"(acc[mi][ni][2]), "+f"(acc[mi][ni][3])
                        : "r"(af[mi][0]), "r"(af[mi][1]), "r"(af[mi][2]), "r"(af[mi][3]),
                          "r"(bf[ni][0]), "r"(bf[ni][1]));
                }
        }

        // ---- issue chunk B of next tile; wait for chunk B of this tile ----
        if (tn < NTILES) {
            stageB(tn, buf ^ 1);                          // pending: B(t),A(tn),B(tn)
            asm volatile("cp.async.wait_group 2;\n");     // B(t) done
        } else {
            asm volatile("cp.async.wait_group 0;\n");
        }
        __syncthreads();

        // ---- k-steps 8..15 (chunk B data) ----
        #pragma unroll
        for (int ks = 8; ks < 16; ks++) {
            const int k0 = ks * 8;
            uint32_t af[2][4];
            #pragma unroll
            for (int mi = 0; mi < 2; mi++) {
                asm volatile(
                    "ldmatrix.sync.aligned.m8n8.x4.shared.b16 {%0,%1,%2,%3}, [%4];\n"
                    : "=r"(af[mi][0]), "=r"(af[mi][1]),
                      "=r"(af[mi][2]), "=r"(af[mi][3])
                    : "r"(sq_u + a_off[mi] + (uint32_t)(k0 * 4)));
            }
            uint32_t bf[2][2];
            #pragma unroll
            for (int ni = 0; ni < 2; ni++) {
                const int cb = wn * 16 + ni * 8 + gid;
                const float* base = &sKV[(k0 + tig) * KS + cb];
                bf[ni][0] = f2tf32(base[0]);
                bf[ni][1] = f2tf32(base[4 * KS]);
            }
            #pragma unroll
            for (int mi = 0; mi < 2; mi++)
                #pragma unroll
                for (int ni = 0; ni < 2; ni++) {
                    asm volatile(
                        "mma.sync.aligned.m16n8k8.row.col.f32.tf32.tf32.f32 "
                        "{%0,%1,%2,%3}, {%4,%5,%6,%7}, {%8,%9}, {%0,%1,%2,%3};\n"
                        : "+f"(acc[mi][ni][0]), "+f"(acc[mi][ni][1]),
                          "+f"(acc[mi][ni][2]), "+f"(acc[mi][ni][3])
                        : "r"(af[mi][0]), "r"(af[mi][1]), "r"(af[mi][2]), "r"(af[mi][3]),
                          "r"(bf[ni][0]), "r"(bf[ni][1]));
                }
        }
        __syncthreads();   // all smem reads of buf done; Q area now reusable as sO

        // ---- epilogue stage 1: decay-scaled fragments -> smem O tile ----
        #pragma unroll
        for (int mi = 0; mi < 2; mi++) {
            const int r0 = wm * 32 + mi * 16 + gid;
            const float d0 = __expf(-sv * (float)(r0 + 1));
            const float d1 = __expf(-sv * (float)(r0 + 9));
            #pragma unroll
            for (int ni = 0; ni < 2; ni++) {
                const int col = wn * 16 + ni * 8 + tig * 2;
                float2 v0 = make_float2(d0 * acc[mi][ni][0], d0 * acc[mi][ni][1]);
                *(float2*)&sO[r0 * OSD + col] = v0;
                float2 v1 = make_float2(d1 * acc[mi][ni][2], d1 * acc[mi][ni][3]);
                *(float2*)&sO[(r0 + 8) * OSD + col] = v1;
            }
        }
        __syncthreads();

        // ---- epilogue stage 2: linear full-line write: out = oin + sO ----
        #pragma unroll
        for (int j = 0; j < 4; j++) {
            int f = tid + j * NT;
            int row = f >> 5, c4 = f & 31;
            float4 v = *(const float4*)&sO[row * OSD + c4 * 4];
            float4 o = oreg[j];
            o.x += v.x; o.y += v.y; o.z += v.z; o.w += v.w;
            *(float4*)&out[(obase + row) * 128 + c4 * 4] = o;
        }
        __syncthreads();   // epilogue smem reads done before next iter stages into buf
    }
}

extern "C" void kernel_launch(void* const* d_in, const int* in_sizes, int n_in,
                              void* d_out, int out_size)
{
    const float* q   = (const float*)d_in[0];
    const float* oin = (const float*)d_in[1];
    const float* s   = (const float*)d_in[2];
    const float* kv  = (const float*)d_in[3];
    float* out = (float*)d_out;

    int dev = 0;
    cudaGetDevice(&dev);
    int nsm = 148;
    cudaDeviceGetAttribute(&nsm, cudaDevAttrMultiProcessorCount, dev);

    cudaFuncSetAttribute(lightning_inter_kernel,
                         cudaFuncAttributeMaxDynamicSharedMemorySize, SMEM_BYTES);

    lightning_inter_kernel<<<nsm, NT, SMEM_BYTES>>>(q, oin, s, kv, out, nsm);
}